// round 10
// baseline (speedup 1.0000x reference)
#include <cuda_runtime.h>
#include <math.h>

// Problem-scale upper bounds (N=50000, Etot=850000)
#define MAXN 50176
#define MAXE 1048576

// ---------------- scratch (device globals) ----------------
__device__ float g_hA[MAXN * 64];
__device__ float g_hB[MAXN * 64];
__device__ float g_fA[MAXN * 64];
__device__ float g_fB[MAXN * 64];
__device__ float g_as[MAXN];
__device__ float g_ad[MAXN];
__device__ int   g_deg[MAXN];
__device__ int   g_offs[MAXN + 1];
__device__ int   g_cursor[MAXN];
__device__ int   g_csr_src[MAXE];
__device__ int   g_csr_eid[MAXE];

__device__ __forceinline__ float* buf_ptr(int id) {
    switch (id) {
        case 0:  return g_hA;
        case 1:  return g_hB;
        case 2:  return g_fA;
        default: return g_fB;
    }
}

// ---------------- CSR build ----------------
__global__ void zero_deg_kernel(int N) {
    int i = blockIdx.x * blockDim.x + threadIdx.x;
    if (i < N) g_deg[i] = 0;
}

// fused: degree histogram + write stacked [src;dst] floats to output head
__global__ void deg_srcdst_kernel(const int* __restrict__ ei, int E, int N,
                                  float* __restrict__ out) {
    int e = blockIdx.x * blockDim.x + threadIdx.x;
    int Etot = E + N;
    if (e >= Etot) return;
    int s, d;
    if (e < E) { s = ei[e]; d = ei[E + e]; }
    else       { s = d = e - E; }
    out[e]        = (float)s;
    out[Etot + e] = (float)d;
    atomicAdd(&g_deg[d], 1);
}

// single block, 1024 threads: chunk-per-thread serial scan + hierarchical block scan
__global__ void scan_kernel(int N) {
    __shared__ int wsum[32];
    int tid  = threadIdx.x;
    int lane = tid & 31, wid = tid >> 5;
    int C = (N + 1023) / 1024;
    int lo = tid * C, hi = min(lo + C, N);

    int local = 0;
    for (int i = lo; i < hi; i++) local += g_deg[i];

    int inc = local;
    #pragma unroll
    for (int o = 1; o < 32; o <<= 1) {
        int v = __shfl_up_sync(0xffffffffu, inc, o);
        if (lane >= o) inc += v;
    }
    if (lane == 31) wsum[wid] = inc;
    __syncthreads();
    if (wid == 0) {
        int w = wsum[lane];
        #pragma unroll
        for (int o = 1; o < 32; o <<= 1) {
            int v = __shfl_up_sync(0xffffffffu, w, o);
            if (lane >= o) w += v;
        }
        wsum[lane] = w;
    }
    __syncthreads();
    int warp_excl = (wid == 0) ? 0 : wsum[wid - 1];
    int excl = warp_excl + inc - local;

    int run = excl;
    for (int i = lo; i < hi; i++) {
        int v = g_deg[i];
        g_offs[i] = run;
        g_cursor[i] = run;
        run += v;
    }
    if (tid == 1023) g_offs[N] = run;
}

__global__ void scatter_kernel(const int* __restrict__ ei, int E, int N) {
    int e = blockIdx.x * blockDim.x + threadIdx.x;
    int Etot = E + N;
    if (e >= Etot) return;
    int s, d;
    if (e < E) { s = ei[e]; d = ei[E + e]; }
    else       { s = e - E; d = e - E; }
    int pos = atomicAdd(&g_cursor[d], 1);
    g_csr_src[pos] = s;
    g_csr_eid[pos] = e;
}

// ---------------- dense GEMM + fused attention scores ----------------
// H[N,FOUT] = X[N,FIN] @ W[FOUT,FIN]^T ;  g_as[n]=H[n,:]·a_s ; g_ad[n]=H[n,:]·a_d
// 256 threads (16x16). Tile = 128 nodes x FOUT. Per-thread 8 nodes x FPT feats.
template <int FIN, int FOUT>
__global__ void gemm_kernel(const float* __restrict__ xptr, int xbuf,
                            const float* __restrict__ W,
                            const float* __restrict__ a_s,
                            const float* __restrict__ a_d,
                            int hbuf, int N) {
    const float* X = xptr ? xptr : buf_ptr(xbuf);
    float* H = buf_ptr(hbuf);

    constexpr int FPT = FOUT / 16;     // 4 or 2
    constexpr int KC  = 32;
    constexpr int XP  = 132;
    constexpr int WP  = FOUT + 4;
    __shared__ float Xs[KC * XP];
    __shared__ float Ws[KC * WP];

    int tid   = threadIdx.x;
    int nbase = blockIdx.x * 128;
    int tx = tid & 15, ty = tid >> 4;
    int lane = tid & 31;
    int f0 = tx * FPT;
    int n0 = ty * 8;

    float acc[8][FPT];
    #pragma unroll
    for (int i = 0; i < 8; i++)
        #pragma unroll
        for (int j = 0; j < FPT; j++) acc[i][j] = 0.f;

    for (int kc = 0; kc < FIN; kc += KC) {
        #pragma unroll
        for (int t = tid; t < 128 * KC; t += 256) {
            int n = t / KC, k = t % KC;
            int gn = nbase + n;
            Xs[k * XP + n] = (gn < N) ? X[gn * FIN + kc + k] : 0.f;
        }
        for (int t = tid; t < FOUT * KC; t += 256) {
            int f = t / KC, k = t % KC;
            Ws[k * WP + f] = W[f * FIN + kc + k];
        }
        __syncthreads();
        #pragma unroll
        for (int k = 0; k < KC; k++) {
            float4 xa = *(const float4*)&Xs[k * XP + n0];
            float4 xb = *(const float4*)&Xs[k * XP + n0 + 4];
            float xv[8] = {xa.x, xa.y, xa.z, xa.w, xb.x, xb.y, xb.z, xb.w};
            float wv[FPT];
            if (FPT == 4) {
                float4 w4 = *(const float4*)&Ws[k * WP + f0];
                wv[0] = w4.x; wv[1] = w4.y; wv[2] = w4.z; wv[3] = w4.w;
            } else {
                float2 w2 = *(const float2*)&Ws[k * WP + f0];
                wv[0] = w2.x; wv[1] = w2.y;
            }
            #pragma unroll
            for (int i = 0; i < 8; i++)
                #pragma unroll
                for (int j = 0; j < FPT; j++)
                    acc[i][j] = fmaf(xv[i], wv[j], acc[i][j]);
        }
        __syncthreads();
    }

    // store H
    #pragma unroll
    for (int i = 0; i < 8; i++) {
        int gn = nbase + n0 + i;
        if (gn < N) {
            #pragma unroll
            for (int j = 0; j < FPT; j++) H[gn * FOUT + f0 + j] = acc[i][j];
        }
    }

    // fused attention scores: per-node dot with a_s/a_d, reduce across 16 tx lanes
    float asv[FPT], adv[FPT];
    #pragma unroll
    for (int j = 0; j < FPT; j++) { asv[j] = a_s[f0 + j]; adv[j] = a_d[f0 + j]; }
    #pragma unroll
    for (int i = 0; i < 8; i++) {
        float ps = 0.f, pd = 0.f;
        #pragma unroll
        for (int j = 0; j < FPT; j++) {
            ps = fmaf(acc[i][j], asv[j], ps);
            pd = fmaf(acc[i][j], adv[j], pd);
        }
        #pragma unroll
        for (int o = 8; o; o >>= 1) {
            ps += __shfl_xor_sync(0xffffffffu, ps, o);
            pd += __shfl_xor_sync(0xffffffffu, pd, o);
        }
        if ((lane & 15) == 0) {
            int gn = nbase + n0 + i;
            if (gn < N) { g_as[gn] = ps; g_ad[gn] = pd; }
        }
    }
}

// ---------------- edge stage: warp per destination, no-max softmax ----------------
template <int F, bool WRITE_ALPHA>
__global__ void edge_kernel(int hbuf, const float* __restrict__ bias,
                            float* __restrict__ optr, int obuf,
                            float* __restrict__ alpha_out, int N, int do_relu) {
    const float* __restrict__ h = buf_ptr(hbuf);
    float* out = optr ? optr : buf_ptr(obuf);

    int warp = (blockIdx.x * blockDim.x + threadIdx.x) >> 5;
    int lane = threadIdx.x & 31;
    if (warp >= N) return;
    int n   = warp;
    int beg = g_offs[n], end = g_offs[n + 1];
    float adv = g_ad[n];

    float lsum = 0.f;            // per-lane partial sum (reduced once at end)
    float acc0 = 0.f, acc1 = 0.f;

    for (int c = beg; c < end; c += 32) {
        int j = c + lane;
        bool valid = (j < end);
        int s = valid ? g_csr_src[j] : 0;
        float e = g_as[s] + adv;
        e = (e > 0.f) ? e : 0.2f * e;
        float ex = valid ? __expf(e) : 0.f;   // scores are O(1); exp safe in fp32
        lsum += ex;
        if (WRITE_ALPHA && valid) alpha_out[g_csr_eid[j]] = ex;   // scaled in tail

        int cnt = end - c;
        if (cnt >= 32) {
            #pragma unroll 8
            for (int t = 0; t < 32; t++) {
                float ext = __shfl_sync(0xffffffffu, ex, t);
                int   st  = __shfl_sync(0xffffffffu, s, t);
                acc0 = fmaf(ext, h[st * F + lane], acc0);
                if (F == 64) acc1 = fmaf(ext, h[st * F + 32 + lane], acc1);
            }
        } else {
            for (int t = 0; t < cnt; t++) {
                float ext = __shfl_sync(0xffffffffu, ex, t);
                int   st  = __shfl_sync(0xffffffffu, s, t);
                acc0 = fmaf(ext, h[st * F + lane], acc0);
                if (F == 64) acc1 = fmaf(ext, h[st * F + 32 + lane], acc1);
            }
        }
    }
    float ssum = lsum;
    #pragma unroll
    for (int o = 16; o; o >>= 1) ssum += __shfl_xor_sync(0xffffffffu, ssum, o);
    float inv = 1.f / (ssum + 1e-16f);

    if (WRITE_ALPHA) {
        for (int j = beg + lane; j < end; j += 32) alpha_out[g_csr_eid[j]] *= inv;
    }

    float o0 = fmaf(acc0, inv, bias[lane]);
    if (do_relu) o0 = fmaxf(o0, 0.f);
    out[n * F + lane] = o0;
    if (F == 64) {
        float o1 = fmaf(acc1, inv, bias[32 + lane]);
        if (do_relu) o1 = fmaxf(o1, 0.f);
        out[n * F + 32 + lane] = o1;
    }
}

// ---------------- launch ----------------
extern "C" void kernel_launch(void* const* d_in, const int* in_sizes, int n_in,
                              void* d_out, int out_size) {
    const float* x  = (const float*)d_in[0];
    const int*   ei = (const int*)d_in[1];       // int32
    const float* W1 = (const float*)d_in[2];
    const float* as1 = (const float*)d_in[3];
    const float* ad1 = (const float*)d_in[4];
    const float* b1 = (const float*)d_in[5];
    const float* W2 = (const float*)d_in[6];
    const float* as2 = (const float*)d_in[7];
    const float* ad2 = (const float*)d_in[8];
    const float* b2 = (const float*)d_in[9];
    const float* W3 = (const float*)d_in[10];
    const float* as3 = (const float*)d_in[11];
    const float* ad3 = (const float*)d_in[12];
    const float* b3 = (const float*)d_in[13];

    int H1   = in_sizes[3];
    int FIN  = in_sizes[2] / H1;
    int N    = in_sizes[0] / FIN;
    int E    = in_sizes[1] / 2;
    int Etot = E + N;

    float* out = (float*)d_out;
    float* out_alpha = out + 2 * (size_t)Etot;
    float* out_feat  = out + 3 * (size_t)Etot;

    const int TB = 256;
    int ebl = (Etot + TB - 1) / TB;
    int nbl = (N + TB - 1) / TB;

    // ---- CSR build (shared by all 3 layers) ----
    zero_deg_kernel<<<nbl, TB>>>(N);
    deg_srcdst_kernel<<<ebl, TB>>>(ei, E, N, out);
    scan_kernel<<<1, 1024>>>(N);
    scatter_kernel<<<ebl, TB>>>(ei, E, N);

    int gemm_bl = (N + 127) / 128;
    int warp_bl = (N * 32 + TB - 1) / TB;

    // buffer ids: 0=g_hA, 1=g_hB, 2=g_fA, 3=g_fB
    // ---- layer 1 ----
    gemm_kernel<128, 64><<<gemm_bl, 256>>>(x, -1, W1, as1, ad1, 0, N);
    edge_kernel<64, true><<<warp_bl, TB>>>(0, b1, nullptr, 2, out_alpha, N, 1);

    // ---- layer 2 ----
    gemm_kernel<64, 64><<<gemm_bl, 256>>>(nullptr, 2, W2, as2, ad2, 1, N);
    edge_kernel<64, false><<<warp_bl, TB>>>(1, b2, nullptr, 3, nullptr, N, 1);

    // ---- layer 3 ----
    gemm_kernel<64, 32><<<gemm_bl, 256>>>(nullptr, 3, W3, as3, ad3, 0, N);
    edge_kernel<32, false><<<warp_bl, TB>>>(0, b3, out_feat, -1, nullptr, N, 0);

    (void)n_in; (void)out_size;
}

// round 11
// speedup vs baseline: 1.0312x; 1.0312x over previous
#include <cuda_runtime.h>
#include <math.h>

// Problem-scale upper bounds (N=50000, Etot=850000)
#define MAXN 50176
#define MAXE 1048576

// ---------------- scratch (device globals) ----------------
__device__ float g_hA[MAXN * 64];
__device__ float g_hB[MAXN * 64];
__device__ float g_fA[MAXN * 64];
__device__ float g_fB[MAXN * 64];
__device__ float g_as[MAXN];
__device__ float g_ad[MAXN];
__device__ int   g_deg[MAXN];
__device__ int   g_offs[MAXN + 1];
__device__ int   g_cursor[MAXN];
__device__ int   g_csr_src[MAXE];
__device__ int   g_csr_eid[MAXE];

__device__ __forceinline__ float* buf_ptr(int id) {
    switch (id) {
        case 0:  return g_hA;
        case 1:  return g_hB;
        case 2:  return g_fA;
        default: return g_fB;
    }
}

// ---------------- GEMM block body (device fn, callable from fused kernels) ----------------
// H[N,FOUT] = X[N,FIN] @ W[FOUT,FIN]^T ; also g_as[n]=H[n,:]·a_s, g_ad[n]=H[n,:]·a_d
// 256 threads (16x16). Tile = 128 nodes x FOUT. Per-thread 8 nodes x FPT feats.
template <int FIN, int FOUT>
__device__ __forceinline__ void gemm_block(const float* __restrict__ X,
                                           const float* __restrict__ W,
                                           const float* __restrict__ a_s,
                                           const float* __restrict__ a_d,
                                           float* __restrict__ H, int N, int nblk) {
    constexpr int FPT = FOUT / 16;     // 4 or 2
    constexpr int KC  = 32;
    constexpr int XP  = 132;
    constexpr int WP  = FOUT + 4;
    __shared__ float Xs[KC * XP];
    __shared__ float Ws[KC * WP];

    int tid   = threadIdx.x;
    int nbase = nblk * 128;
    int tx = tid & 15, ty = tid >> 4;
    int lane = tid & 31;
    int f0 = tx * FPT;
    int n0 = ty * 8;

    float acc[8][FPT];
    #pragma unroll
    for (int i = 0; i < 8; i++)
        #pragma unroll
        for (int j = 0; j < FPT; j++) acc[i][j] = 0.f;

    for (int kc = 0; kc < FIN; kc += KC) {
        #pragma unroll
        for (int t = tid; t < 128 * KC; t += 256) {
            int n = t / KC, k = t % KC;
            int gn = nbase + n;
            Xs[k * XP + n] = (gn < N) ? X[gn * FIN + kc + k] : 0.f;
        }
        for (int t = tid; t < FOUT * KC; t += 256) {
            int f = t / KC, k = t % KC;
            Ws[k * WP + f] = W[f * FIN + kc + k];
        }
        __syncthreads();
        #pragma unroll
        for (int k = 0; k < KC; k++) {
            float4 xa = *(const float4*)&Xs[k * XP + n0];
            float4 xb = *(const float4*)&Xs[k * XP + n0 + 4];
            float xv[8] = {xa.x, xa.y, xa.z, xa.w, xb.x, xb.y, xb.z, xb.w};
            float wv[FPT];
            if (FPT == 4) {
                float4 w4 = *(const float4*)&Ws[k * WP + f0];
                wv[0] = w4.x; wv[1] = w4.y; wv[2] = w4.z; wv[3] = w4.w;
            } else {
                float2 w2 = *(const float2*)&Ws[k * WP + f0];
                wv[0] = w2.x; wv[1] = w2.y;
            }
            #pragma unroll
            for (int i = 0; i < 8; i++)
                #pragma unroll
                for (int j = 0; j < FPT; j++)
                    acc[i][j] = fmaf(xv[i], wv[j], acc[i][j]);
        }
        __syncthreads();
    }

    #pragma unroll
    for (int i = 0; i < 8; i++) {
        int gn = nbase + n0 + i;
        if (gn < N) {
            #pragma unroll
            for (int j = 0; j < FPT; j++) H[gn * FOUT + f0 + j] = acc[i][j];
        }
    }

    // fused attention scores
    float asv[FPT], adv[FPT];
    #pragma unroll
    for (int j = 0; j < FPT; j++) { asv[j] = a_s[f0 + j]; adv[j] = a_d[f0 + j]; }
    #pragma unroll
    for (int i = 0; i < 8; i++) {
        float ps = 0.f, pd = 0.f;
        #pragma unroll
        for (int j = 0; j < FPT; j++) {
            ps = fmaf(acc[i][j], asv[j], ps);
            pd = fmaf(acc[i][j], adv[j], pd);
        }
        #pragma unroll
        for (int o = 8; o; o >>= 1) {
            ps += __shfl_xor_sync(0xffffffffu, ps, o);
            pd += __shfl_xor_sync(0xffffffffu, pd, o);
        }
        if ((lane & 15) == 0) {
            int gn = nbase + n0 + i;
            if (gn < N) { g_as[gn] = ps; g_ad[gn] = pd; }
        }
    }
}

// ---------------- CSR build pieces ----------------
__global__ void zero_deg_kernel(int N) {
    int i = blockIdx.x * blockDim.x + threadIdx.x;
    if (i < N) g_deg[i] = 0;
}

// fused launch A: first gemmBlocks blocks run layer-1 GEMM (tiles [0,gemmBlocks));
// remaining blocks do degree histogram + [src;dst] float writeback.
__global__ void fusedA_kernel(const int* __restrict__ ei, int E, int N,
                              float* __restrict__ out,
                              const float* __restrict__ X, const float* __restrict__ W1,
                              const float* __restrict__ a_s, const float* __restrict__ a_d,
                              int gemmBlocks) {
    if ((int)blockIdx.x < gemmBlocks) {
        gemm_block<128, 64>(X, W1, a_s, a_d, g_hA, N, blockIdx.x);
        return;
    }
    int e = (blockIdx.x - gemmBlocks) * blockDim.x + threadIdx.x;
    int Etot = E + N;
    if (e >= Etot) return;
    int s, d;
    if (e < E) { s = ei[e]; d = ei[E + e]; }
    else       { s = d = e - E; }
    out[e]        = (float)s;
    out[Etot + e] = (float)d;
    atomicAdd(&g_deg[d], 1);
}

// single block, 1024 threads: chunk-per-thread serial scan + hierarchical block scan
__global__ void scan_kernel(int N) {
    __shared__ int wsum[32];
    int tid  = threadIdx.x;
    int lane = tid & 31, wid = tid >> 5;
    int C = (N + 1023) / 1024;
    int lo = tid * C, hi = min(lo + C, N);

    int local = 0;
    for (int i = lo; i < hi; i++) local += g_deg[i];

    int inc = local;
    #pragma unroll
    for (int o = 1; o < 32; o <<= 1) {
        int v = __shfl_up_sync(0xffffffffu, inc, o);
        if (lane >= o) inc += v;
    }
    if (lane == 31) wsum[wid] = inc;
    __syncthreads();
    if (wid == 0) {
        int w = wsum[lane];
        #pragma unroll
        for (int o = 1; o < 32; o <<= 1) {
            int v = __shfl_up_sync(0xffffffffu, w, o);
            if (lane >= o) w += v;
        }
        wsum[lane] = w;
    }
    __syncthreads();
    int warp_excl = (wid == 0) ? 0 : wsum[wid - 1];
    int excl = warp_excl + inc - local;

    int run = excl;
    for (int i = lo; i < hi; i++) {
        int v = g_deg[i];
        g_offs[i] = run;
        g_cursor[i] = run;
        run += v;
    }
    if (tid == 1023) g_offs[N] = run;
}

// fused launch B: first gemmBlocks blocks run layer-1 GEMM tiles [gemmOffset, ...);
// remaining blocks do the CSR scatter.
__global__ void fusedB_kernel(const int* __restrict__ ei, int E, int N,
                              const float* __restrict__ X, const float* __restrict__ W1,
                              const float* __restrict__ a_s, const float* __restrict__ a_d,
                              int gemmBlocks, int gemmOffset) {
    if ((int)blockIdx.x < gemmBlocks) {
        gemm_block<128, 64>(X, W1, a_s, a_d, g_hA, N, gemmOffset + blockIdx.x);
        return;
    }
    int e = (blockIdx.x - gemmBlocks) * blockDim.x + threadIdx.x;
    int Etot = E + N;
    if (e >= Etot) return;
    int s, d;
    if (e < E) { s = ei[e]; d = ei[E + e]; }
    else       { s = e - E; d = e - E; }
    int pos = atomicAdd(&g_cursor[d], 1);
    g_csr_src[pos] = s;
    g_csr_eid[pos] = e;
}

// plain GEMM wrapper (layers 2, 3)
template <int FIN, int FOUT>
__global__ void gemm_kernel(int xbuf, const float* __restrict__ W,
                            const float* __restrict__ a_s, const float* __restrict__ a_d,
                            int hbuf, int N) {
    gemm_block<FIN, FOUT>(buf_ptr(xbuf), W, a_s, a_d, buf_ptr(hbuf), N, blockIdx.x);
}

// ---------------- edge stage, F=64: warp/dst, lanes own 2 feats (float2 gathers) ----------------
template <bool WRITE_ALPHA>
__global__ void edge64_kernel(int hbuf, const float* __restrict__ bias,
                              float* __restrict__ optr, int obuf,
                              float* __restrict__ alpha_out, int N, int do_relu) {
    const float2* __restrict__ h2 = (const float2*)buf_ptr(hbuf);
    float* outp = optr ? optr : buf_ptr(obuf);

    int warp = (blockIdx.x * blockDim.x + threadIdx.x) >> 5;
    int lane = threadIdx.x & 31;
    if (warp >= N) return;
    int n   = warp;
    int beg = g_offs[n], end = g_offs[n + 1];
    float adv = g_ad[n];

    float lsum = 0.f;
    float ax = 0.f, ay = 0.f;

    for (int c = beg; c < end; c += 32) {
        int j = c + lane;
        bool valid = (j < end);
        int s = valid ? g_csr_src[j] : 0;
        float e = g_as[s] + adv;
        e = (e > 0.f) ? e : 0.2f * e;
        float ex = valid ? __expf(e) : 0.f;
        lsum += ex;
        if (WRITE_ALPHA && valid) alpha_out[g_csr_eid[j]] = ex;

        int cnt = end - c;
        if (cnt >= 32) {
            #pragma unroll 8
            for (int t = 0; t < 32; t++) {
                float ext = __shfl_sync(0xffffffffu, ex, t);
                int   st  = __shfl_sync(0xffffffffu, s, t);
                float2 hv = h2[st * 32 + lane];
                ax = fmaf(ext, hv.x, ax);
                ay = fmaf(ext, hv.y, ay);
            }
        } else {
            for (int t = 0; t < cnt; t++) {
                float ext = __shfl_sync(0xffffffffu, ex, t);
                int   st  = __shfl_sync(0xffffffffu, s, t);
                float2 hv = h2[st * 32 + lane];
                ax = fmaf(ext, hv.x, ax);
                ay = fmaf(ext, hv.y, ay);
            }
        }
    }
    float ssum = lsum;
    #pragma unroll
    for (int o = 16; o; o >>= 1) ssum += __shfl_xor_sync(0xffffffffu, ssum, o);
    float inv = 1.f / (ssum + 1e-16f);

    if (WRITE_ALPHA) {
        for (int j = beg + lane; j < end; j += 32) alpha_out[g_csr_eid[j]] *= inv;
    }

    float2 o2;
    o2.x = fmaf(ax, inv, bias[2 * lane]);
    o2.y = fmaf(ay, inv, bias[2 * lane + 1]);
    if (do_relu) { o2.x = fmaxf(o2.x, 0.f); o2.y = fmaxf(o2.y, 0.f); }
    ((float2*)outp)[n * 32 + lane] = o2;
}

// ---------------- edge stage, F=32: warp/dst, lane owns 1 feat ----------------
__global__ void edge32_kernel(int hbuf, const float* __restrict__ bias,
                              float* __restrict__ optr, int N, int do_relu) {
    const float* __restrict__ h = buf_ptr(hbuf);
    int warp = (blockIdx.x * blockDim.x + threadIdx.x) >> 5;
    int lane = threadIdx.x & 31;
    if (warp >= N) return;
    int n   = warp;
    int beg = g_offs[n], end = g_offs[n + 1];
    float adv = g_ad[n];

    float lsum = 0.f, acc = 0.f;
    for (int c = beg; c < end; c += 32) {
        int j = c + lane;
        bool valid = (j < end);
        int s = valid ? g_csr_src[j] : 0;
        float e = g_as[s] + adv;
        e = (e > 0.f) ? e : 0.2f * e;
        float ex = valid ? __expf(e) : 0.f;
        lsum += ex;

        int cnt = end - c;
        if (cnt >= 32) {
            #pragma unroll 8
            for (int t = 0; t < 32; t++) {
                float ext = __shfl_sync(0xffffffffu, ex, t);
                int   st  = __shfl_sync(0xffffffffu, s, t);
                acc = fmaf(ext, h[st * 32 + lane], acc);
            }
        } else {
            for (int t = 0; t < cnt; t++) {
                float ext = __shfl_sync(0xffffffffu, ex, t);
                int   st  = __shfl_sync(0xffffffffu, s, t);
                acc = fmaf(ext, h[st * 32 + lane], acc);
            }
        }
    }
    float ssum = lsum;
    #pragma unroll
    for (int o = 16; o; o >>= 1) ssum += __shfl_xor_sync(0xffffffffu, ssum, o);
    float inv = 1.f / (ssum + 1e-16f);

    float o0 = fmaf(acc, inv, bias[lane]);
    if (do_relu) o0 = fmaxf(o0, 0.f);
    optr[n * 32 + lane] = o0;
}

// ---------------- launch ----------------
extern "C" void kernel_launch(void* const* d_in, const int* in_sizes, int n_in,
                              void* d_out, int out_size) {
    const float* x  = (const float*)d_in[0];
    const int*   ei = (const int*)d_in[1];       // int32
    const float* W1 = (const float*)d_in[2];
    const float* as1 = (const float*)d_in[3];
    const float* ad1 = (const float*)d_in[4];
    const float* b1 = (const float*)d_in[5];
    const float* W2 = (const float*)d_in[6];
    const float* as2 = (const float*)d_in[7];
    const float* ad2 = (const float*)d_in[8];
    const float* b2 = (const float*)d_in[9];
    const float* W3 = (const float*)d_in[10];
    const float* as3 = (const float*)d_in[11];
    const float* ad3 = (const float*)d_in[12];
    const float* b3 = (const float*)d_in[13];

    int H1   = in_sizes[3];
    int FIN  = in_sizes[2] / H1;
    int N    = in_sizes[0] / FIN;
    int E    = in_sizes[1] / 2;
    int Etot = E + N;

    float* out = (float*)d_out;
    float* out_alpha = out + 2 * (size_t)Etot;
    float* out_feat  = out + 3 * (size_t)Etot;

    const int TB = 256;
    int ebl = (Etot + TB - 1) / TB;
    int nbl = (N + TB - 1) / TB;

    int gemm_bl = (N + 127) / 128;
    int gA = gemm_bl / 2;            // layer-1 GEMM tiles fused with deg pass
    int gB = gemm_bl - gA;           // rest fused with scatter pass
    int warp_bl = (N * 32 + TB - 1) / TB;

    // ---- prologue: CSR build overlapped with layer-1 GEMM ----
    zero_deg_kernel<<<nbl, TB>>>(N);
    fusedA_kernel<<<gA + ebl, TB>>>(ei, E, N, out, x, W1, as1, ad1, gA);
    scan_kernel<<<1, 1024>>>(N);
    fusedB_kernel<<<gB + ebl, TB>>>(ei, E, N, x, W1, as1, ad1, gB, gA);

    // buffer ids: 0=g_hA, 1=g_hB, 2=g_fA, 3=g_fB
    // ---- layer 1 edge ----
    edge64_kernel<true><<<warp_bl, TB>>>(0, b1, nullptr, 2, out_alpha, N, 1);

    // ---- layer 2 ----
    gemm_kernel<64, 64><<<gemm_bl, 256>>>(2, W2, as2, ad2, 1, N);
    edge64_kernel<false><<<warp_bl, TB>>>(1, b2, nullptr, 3, nullptr, N, 1);

    // ---- layer 3 ----
    gemm_kernel<64, 32><<<gemm_bl, 256>>>(3, W3, as3, ad3, 0, N);
    edge32_kernel<<<warp_bl, TB>>>(0, b3, out_feat, N, 0);

    (void)n_in; (void)out_size;
}

// round 16
// speedup vs baseline: 1.1066x; 1.0731x over previous
#include <cuda_runtime.h>
#include <math.h>

// Problem-scale upper bounds (N=50000, Etot=850000)
#define MAXN 50176
#define MAXE 1048576

// ---------------- scratch (device globals, 16B-aligned for float4) ----------------
__device__ __align__(16) float g_hA[MAXN * 64];
__device__ __align__(16) float g_hB[MAXN * 64];
__device__ __align__(16) float g_fA[MAXN * 64];
__device__ __align__(16) float g_fB[MAXN * 64];
__device__ float g_as[MAXN];
__device__ float g_ad[MAXN];
__device__ int   g_deg[MAXN];
__device__ int   g_offs[MAXN + 1];
__device__ int   g_cursor[MAXN];
__device__ int   g_csr_src[MAXE];
__device__ int   g_csr_eid[MAXE];

__device__ __forceinline__ float* buf_ptr(int id) {
    switch (id) {
        case 0:  return g_hA;
        case 1:  return g_hB;
        case 2:  return g_fA;
        default: return g_fB;
    }
}

// ---------------- CSR build (lightweight, high-occupancy kernels) ----------------
__global__ void zero_deg_kernel(int N) {
    int i = blockIdx.x * blockDim.x + threadIdx.x;
    if (i < N) g_deg[i] = 0;
}

// fused: degree histogram + write stacked [src;dst] floats to output head
__global__ void deg_srcdst_kernel(const int* __restrict__ ei, int E, int N,
                                  float* __restrict__ out) {
    int e = blockIdx.x * blockDim.x + threadIdx.x;
    int Etot = E + N;
    if (e >= Etot) return;
    int s, d;
    if (e < E) { s = ei[e]; d = ei[E + e]; }
    else       { s = d = e - E; }
    out[e]        = (float)s;
    out[Etot + e] = (float)d;
    atomicAdd(&g_deg[d], 1);
}

// single block, 1024 threads: chunk-per-thread serial scan + hierarchical block scan
__global__ void scan_kernel(int N) {
    __shared__ int wsum[32];
    int tid  = threadIdx.x;
    int lane = tid & 31, wid = tid >> 5;
    int C = (N + 1023) / 1024;
    int lo = tid * C, hi = min(lo + C, N);

    int local = 0;
    for (int i = lo; i < hi; i++) local += g_deg[i];

    int inc = local;
    #pragma unroll
    for (int o = 1; o < 32; o <<= 1) {
        int v = __shfl_up_sync(0xffffffffu, inc, o);
        if (lane >= o) inc += v;
    }
    if (lane == 31) wsum[wid] = inc;
    __syncthreads();
    if (wid == 0) {
        int w = wsum[lane];
        #pragma unroll
        for (int o = 1; o < 32; o <<= 1) {
            int v = __shfl_up_sync(0xffffffffu, w, o);
            if (lane >= o) w += v;
        }
        wsum[lane] = w;
    }
    __syncthreads();
    int warp_excl = (wid == 0) ? 0 : wsum[wid - 1];
    int excl = warp_excl + inc - local;

    int run = excl;
    for (int i = lo; i < hi; i++) {
        int v = g_deg[i];
        g_offs[i] = run;
        g_cursor[i] = run;
        run += v;
    }
    if (tid == 1023) g_offs[N] = run;
}

__global__ void scatter_kernel(const int* __restrict__ ei, int E, int N) {
    int e = blockIdx.x * blockDim.x + threadIdx.x;
    int Etot = E + N;
    if (e >= Etot) return;
    int s, d;
    if (e < E) { s = ei[e]; d = ei[E + e]; }
    else       { s = e - E; d = e - E; }
    int pos = atomicAdd(&g_cursor[d], 1);
    g_csr_src[pos] = s;
    g_csr_eid[pos] = e;
}

// ---------------- dense GEMM + fused attention scores ----------------
// H[N,FOUT] = X[N,FIN] @ W[FOUT,FIN]^T ; g_as[n]=H[n,:]·a_s ; g_ad[n]=H[n,:]·a_d
template <int FIN, int FOUT>
__global__ void gemm_kernel(const float* __restrict__ xptr, int xbuf,
                            const float* __restrict__ W,
                            const float* __restrict__ a_s,
                            const float* __restrict__ a_d,
                            int hbuf, int N) {
    const float* X = xptr ? xptr : buf_ptr(xbuf);
    float* H = buf_ptr(hbuf);

    constexpr int FPT = FOUT / 16;     // 4 or 2
    constexpr int KC  = 32;
    constexpr int XP  = 132;
    constexpr int WP  = FOUT + 4;
    __shared__ float Xs[KC * XP];
    __shared__ float Ws[KC * WP];

    int tid   = threadIdx.x;
    int nbase = blockIdx.x * 128;
    int tx = tid & 15, ty = tid >> 4;
    int lane = tid & 31;
    int f0 = tx * FPT;
    int n0 = ty * 8;

    float acc[8][FPT];
    #pragma unroll
    for (int i = 0; i < 8; i++)
        #pragma unroll
        for (int j = 0; j < FPT; j++) acc[i][j] = 0.f;

    for (int kc = 0; kc < FIN; kc += KC) {
        #pragma unroll
        for (int t = tid; t < 128 * KC; t += 256) {
            int n = t / KC, k = t % KC;
            int gn = nbase + n;
            Xs[k * XP + n] = (gn < N) ? X[gn * FIN + kc + k] : 0.f;
        }
        for (int t = tid; t < FOUT * KC; t += 256) {
            int f = t / KC, k = t % KC;
            Ws[k * WP + f] = W[f * FIN + kc + k];
        }
        __syncthreads();
        #pragma unroll
        for (int k = 0; k < KC; k++) {
            float4 xa = *(const float4*)&Xs[k * XP + n0];
            float4 xb = *(const float4*)&Xs[k * XP + n0 + 4];
            float xv[8] = {xa.x, xa.y, xa.z, xa.w, xb.x, xb.y, xb.z, xb.w};
            float wv[FPT];
            if (FPT == 4) {
                float4 w4 = *(const float4*)&Ws[k * WP + f0];
                wv[0] = w4.x; wv[1] = w4.y; wv[2] = w4.z; wv[3] = w4.w;
            } else {
                float2 w2 = *(const float2*)&Ws[k * WP + f0];
                wv[0] = w2.x; wv[1] = w2.y;
            }
            #pragma unroll
            for (int i = 0; i < 8; i++)
                #pragma unroll
                for (int j = 0; j < FPT; j++)
                    acc[i][j] = fmaf(xv[i], wv[j], acc[i][j]);
        }
        __syncthreads();
    }

    #pragma unroll
    for (int i = 0; i < 8; i++) {
        int gn = nbase + n0 + i;
        if (gn < N) {
            #pragma unroll
            for (int j = 0; j < FPT; j++) H[gn * FOUT + f0 + j] = acc[i][j];
        }
    }

    // fused attention scores
    float asv[FPT], adv[FPT];
    #pragma unroll
    for (int j = 0; j < FPT; j++) { asv[j] = a_s[f0 + j]; adv[j] = a_d[f0 + j]; }
    #pragma unroll
    for (int i = 0; i < 8; i++) {
        float ps = 0.f, pd = 0.f;
        #pragma unroll
        for (int j = 0; j < FPT; j++) {
            ps = fmaf(acc[i][j], asv[j], ps);
            pd = fmaf(acc[i][j], adv[j], pd);
        }
        #pragma unroll
        for (int o = 8; o; o >>= 1) {
            ps += __shfl_xor_sync(0xffffffffu, ps, o);
            pd += __shfl_xor_sync(0xffffffffu, pd, o);
        }
        if ((lane & 15) == 0) {
            int gn = nbase + n0 + i;
            if (gn < N) { g_as[gn] = ps; g_ad[gn] = pd; }
        }
    }
}

// ---------------- edge stage, F=64: 16 lanes per node, float4 gathers ----------------
// NOTE: two independent nodes per warp -> groups diverge; ALL shuffles must use
// the segment-local member mask, not 0xffffffff.
template <bool WRITE_ALPHA>
__global__ void edge64_kernel(int hbuf, const float* __restrict__ bias,
                              float* __restrict__ optr, int obuf,
                              float* __restrict__ alpha_out, int N, int do_relu) {
    const float4* __restrict__ h4 = (const float4*)buf_ptr(hbuf);
    float* outp = optr ? optr : buf_ptr(obuf);

    int gid = (blockIdx.x * blockDim.x + threadIdx.x) >> 4;   // node (group) id
    int l   = threadIdx.x & 15;                               // lane within group
    unsigned gmask = 0xFFFFu << (threadIdx.x & 16);           // this group's lanes
    if (gid >= N) return;
    int beg = g_offs[gid], end = g_offs[gid + 1];
    float adv = g_ad[gid];

    float lsum = 0.f;
    float4 acc = make_float4(0.f, 0.f, 0.f, 0.f);

    for (int c = beg; c < end; c += 16) {
        int j = c + l;
        bool valid = (j < end);
        int s = valid ? g_csr_src[j] : 0;
        float e = g_as[s] + adv;
        e = (e > 0.f) ? e : 0.2f * e;
        float ex = valid ? __expf(e) : 0.f;
        lsum += ex;
        if (WRITE_ALPHA && valid) alpha_out[g_csr_eid[j]] = ex;

        int cnt = min(16, end - c);
        #pragma unroll 4
        for (int t = 0; t < cnt; t++) {
            float ext = __shfl_sync(gmask, ex, t, 16);
            int   st  = __shfl_sync(gmask, s, t, 16);
            float4 hv = h4[st * 16 + l];
            acc.x = fmaf(ext, hv.x, acc.x);
            acc.y = fmaf(ext, hv.y, acc.y);
            acc.z = fmaf(ext, hv.z, acc.z);
            acc.w = fmaf(ext, hv.w, acc.w);
        }
    }
    float ssum = lsum;
    #pragma unroll
    for (int o = 8; o; o >>= 1) ssum += __shfl_xor_sync(gmask, ssum, o, 16);
    float inv = 1.f / (ssum + 1e-16f);

    if (WRITE_ALPHA) {
        for (int j = beg + l; j < end; j += 16) alpha_out[g_csr_eid[j]] *= inv;
    }

    float4 b4 = ((const float4*)bias)[l];
    float4 o4;
    o4.x = fmaf(acc.x, inv, b4.x);
    o4.y = fmaf(acc.y, inv, b4.y);
    o4.z = fmaf(acc.z, inv, b4.z);
    o4.w = fmaf(acc.w, inv, b4.w);
    if (do_relu) {
        o4.x = fmaxf(o4.x, 0.f); o4.y = fmaxf(o4.y, 0.f);
        o4.z = fmaxf(o4.z, 0.f); o4.w = fmaxf(o4.w, 0.f);
    }
    ((float4*)outp)[gid * 16 + l] = o4;
}

// ---------------- edge stage, F=32: 8 lanes per node, float4 gathers ----------------
__global__ void edge32_kernel(int hbuf, const float* __restrict__ bias,
                              float* __restrict__ optr, int N, int do_relu) {
    const float4* __restrict__ h4 = (const float4*)buf_ptr(hbuf);

    int gid = (blockIdx.x * blockDim.x + threadIdx.x) >> 3;
    int l   = threadIdx.x & 7;
    unsigned gmask = 0xFFu << (threadIdx.x & 24);             // this group's lanes
    if (gid >= N) return;
    int beg = g_offs[gid], end = g_offs[gid + 1];
    float adv = g_ad[gid];

    float lsum = 0.f;
    float4 acc = make_float4(0.f, 0.f, 0.f, 0.f);

    for (int c = beg; c < end; c += 8) {
        int j = c + l;
        bool valid = (j < end);
        int s = valid ? g_csr_src[j] : 0;
        float e = g_as[s] + adv;
        e = (e > 0.f) ? e : 0.2f * e;
        float ex = valid ? __expf(e) : 0.f;
        lsum += ex;

        int cnt = min(8, end - c);
        #pragma unroll 4
        for (int t = 0; t < cnt; t++) {
            float ext = __shfl_sync(gmask, ex, t, 8);
            int   st  = __shfl_sync(gmask, s, t, 8);
            float4 hv = h4[st * 8 + l];
            acc.x = fmaf(ext, hv.x, acc.x);
            acc.y = fmaf(ext, hv.y, acc.y);
            acc.z = fmaf(ext, hv.z, acc.z);
            acc.w = fmaf(ext, hv.w, acc.w);
        }
    }
    float ssum = lsum;
    #pragma unroll
    for (int o = 4; o; o >>= 1) ssum += __shfl_xor_sync(gmask, ssum, o, 8);
    float inv = 1.f / (ssum + 1e-16f);

    float4 b4 = ((const float4*)bias)[l];
    float4 o4;
    o4.x = fmaf(acc.x, inv, b4.x);
    o4.y = fmaf(acc.y, inv, b4.y);
    o4.z = fmaf(acc.z, inv, b4.z);
    o4.w = fmaf(acc.w, inv, b4.w);
    if (do_relu) {
        o4.x = fmaxf(o4.x, 0.f); o4.y = fmaxf(o4.y, 0.f);
        o4.z = fmaxf(o4.z, 0.f); o4.w = fmaxf(o4.w, 0.f);
    }
    ((float4*)optr)[gid * 8 + l] = o4;
}

// ---------------- launch ----------------
extern "C" void kernel_launch(void* const* d_in, const int* in_sizes, int n_in,
                              void* d_out, int out_size) {
    const float* x  = (const float*)d_in[0];
    const int*   ei = (const int*)d_in[1];       // int32
    const float* W1 = (const float*)d_in[2];
    const float* as1 = (const float*)d_in[3];
    const float* ad1 = (const float*)d_in[4];
    const float* b1 = (const float*)d_in[5];
    const float* W2 = (const float*)d_in[6];
    const float* as2 = (const float*)d_in[7];
    const float* ad2 = (const float*)d_in[8];
    const float* b2 = (const float*)d_in[9];
    const float* W3 = (const float*)d_in[10];
    const float* as3 = (const float*)d_in[11];
    const float* ad3 = (const float*)d_in[12];
    const float* b3 = (const float*)d_in[13];

    int H1   = in_sizes[3];
    int FIN  = in_sizes[2] / H1;
    int N    = in_sizes[0] / FIN;
    int E    = in_sizes[1] / 2;
    int Etot = E + N;

    float* out = (float*)d_out;
    float* out_alpha = out + 2 * (size_t)Etot;
    float* out_feat  = out + 3 * (size_t)Etot;

    const int TB = 256;
    int ebl = (Etot + TB - 1) / TB;
    int nbl = (N + TB - 1) / TB;

    // ---- CSR build (lightweight kernels, full occupancy) ----
    zero_deg_kernel<<<nbl, TB>>>(N);
    deg_srcdst_kernel<<<ebl, TB>>>(ei, E, N, out);
    scan_kernel<<<1, 1024>>>(N);
    scatter_kernel<<<ebl, TB>>>(ei, E, N);

    int gemm_bl = (N + 127) / 128;
    int g16_bl = (N * 16 + TB - 1) / TB;   // 16 lanes per node
    int g8_bl  = (N * 8 + TB - 1) / TB;    // 8 lanes per node

    // buffer ids: 0=g_hA, 1=g_hB, 2=g_fA, 3=g_fB
    // ---- layer 1 ----
    gemm_kernel<128, 64><<<gemm_bl, 256>>>(x, -1, W1, as1, ad1, 0, N);
    edge64_kernel<true><<<g16_bl, TB>>>(0, b1, nullptr, 2, out_alpha, N, 1);

    // ---- layer 2 ----
    gemm_kernel<64, 64><<<gemm_bl, 256>>>(nullptr, 2, W2, as2, ad2, 1, N);
    edge64_kernel<false><<<g16_bl, TB>>>(1, b2, nullptr, 3, nullptr, N, 1);

    // ---- layer 3 ----
    gemm_kernel<64, 32><<<gemm_bl, 256>>>(nullptr, 3, W3, as3, ad3, 0, N);
    edge32_kernel<<<g8_bl, TB>>>(0, b3, out_feat, N, 0);

    (void)n_in; (void)out_size;
}